// round 1
// baseline (speedup 1.0000x reference)
#include <cuda_runtime.h>
#include <math.h>

// Problem dims (fixed by the reference)
#define B_SZ   4
#define S_LEN  2048
#define D_DIM  1024
#define NHEAD  16
#define DK_DIM 64
#define DFF_D  4096
#define M_ROWS 8192   // B*S

// ---------------- scratch (static __device__ arrays; no allocation) -------
__device__ float g_q  [M_ROWS * D_DIM];
__device__ float g_k  [M_ROWS * D_DIM];
__device__ float g_v  [M_ROWS * D_DIM];
__device__ float g_ctx[M_ROWS * D_DIM];
__device__ float g_y1 [M_ROWS * D_DIM];
__device__ float g_x1 [M_ROWS * D_DIM];
__device__ float g_h  [M_ROWS * DFF_D];
__device__ float g_y2 [M_ROWS * D_DIM];

// ---------------- SGEMM: C[M,N] = A[M,K] @ W[N,K]^T + bias (+res)(+relu) --
// 128x128 block tile, BK=8, 256 threads, 8x8 per-thread microtile.
template<bool RELU, bool RES>
__global__ __launch_bounds__(256)
void sgemm_bias(const float* __restrict__ A,
                const float* __restrict__ W,
                const float* __restrict__ bias,
                const float* __restrict__ Rp,
                float* __restrict__ C,
                int M, int N, int K)
{
    __shared__ float As[8][128];
    __shared__ float Bs[8][128];

    const int tid = threadIdx.x;
    const int bx  = blockIdx.x;   // N tile
    const int by  = blockIdx.y;   // M tile

    const int ldRow = tid >> 1;          // 0..127
    const int ldCol = (tid & 1) * 4;     // 0 or 4

    const float* Aptr = A + (size_t)(by * 128 + ldRow) * K + ldCol;
    const float* Wptr = W + (size_t)(bx * 128 + ldRow) * K + ldCol;

    const int ty = tid >> 4;   // 0..15
    const int tx = tid & 15;   // 0..15

    float acc[8][8];
#pragma unroll
    for (int i = 0; i < 8; i++)
#pragma unroll
        for (int j = 0; j < 8; j++) acc[i][j] = 0.f;

    for (int k0 = 0; k0 < K; k0 += 8) {
        float4 av = *(const float4*)(Aptr + k0);
        float4 wv = *(const float4*)(Wptr + k0);
        __syncthreads();
        As[ldCol + 0][ldRow] = av.x;
        As[ldCol + 1][ldRow] = av.y;
        As[ldCol + 2][ldRow] = av.z;
        As[ldCol + 3][ldRow] = av.w;
        Bs[ldCol + 0][ldRow] = wv.x;
        Bs[ldCol + 1][ldRow] = wv.y;
        Bs[ldCol + 2][ldRow] = wv.z;
        Bs[ldCol + 3][ldRow] = wv.w;
        __syncthreads();

#pragma unroll
        for (int kk = 0; kk < 8; kk++) {
            float4 a0 = *(const float4*)&As[kk][ty * 8];
            float4 a1 = *(const float4*)&As[kk][ty * 8 + 4];
            float4 b0 = *(const float4*)&Bs[kk][tx * 8];
            float4 b1 = *(const float4*)&Bs[kk][tx * 8 + 4];
            float ra[8] = {a0.x, a0.y, a0.z, a0.w, a1.x, a1.y, a1.z, a1.w};
            float rb[8] = {b0.x, b0.y, b0.z, b0.w, b1.x, b1.y, b1.z, b1.w};
#pragma unroll
            for (int i = 0; i < 8; i++)
#pragma unroll
                for (int j = 0; j < 8; j++)
                    acc[i][j] += ra[i] * rb[j];
        }
    }

    // epilogue: bias + optional residual + optional relu, vectorized stores
    const int nBase = bx * 128 + tx * 8;
    float4 blo = *(const float4*)&bias[nBase];
    float4 bhi = *(const float4*)&bias[nBase + 4];
#pragma unroll
    for (int i = 0; i < 8; i++) {
        const int m = by * 128 + ty * 8 + i;
        float4 lo, hi;
        lo.x = acc[i][0] + blo.x;  lo.y = acc[i][1] + blo.y;
        lo.z = acc[i][2] + blo.z;  lo.w = acc[i][3] + blo.w;
        hi.x = acc[i][4] + bhi.x;  hi.y = acc[i][5] + bhi.y;
        hi.z = acc[i][6] + bhi.z;  hi.w = acc[i][7] + bhi.w;
        if (RES) {
            float4 rlo = *(const float4*)&Rp[(size_t)m * N + nBase];
            float4 rhi = *(const float4*)&Rp[(size_t)m * N + nBase + 4];
            lo.x += rlo.x; lo.y += rlo.y; lo.z += rlo.z; lo.w += rlo.w;
            hi.x += rhi.x; hi.y += rhi.y; hi.z += rhi.z; hi.w += rhi.w;
        }
        if (RELU) {
            lo.x = fmaxf(lo.x, 0.f); lo.y = fmaxf(lo.y, 0.f);
            lo.z = fmaxf(lo.z, 0.f); lo.w = fmaxf(lo.w, 0.f);
            hi.x = fmaxf(hi.x, 0.f); hi.y = fmaxf(hi.y, 0.f);
            hi.z = fmaxf(hi.z, 0.f); hi.w = fmaxf(hi.w, 0.f);
        }
        *(float4*)&C[(size_t)m * N + nBase]     = lo;
        *(float4*)&C[(size_t)m * N + nBase + 4] = hi;
    }
}

// ---------------- Flash-style attention --------------------------------
// grid = (S/64, B*H), 64 threads/block. Thread t owns query row (qtile + t):
// q row (64 f32) and output acc (64 f32) live in registers; K/V 64x64 tiles
// stream through shared memory (broadcast reads across the block).
__global__ __launch_bounds__(64)
void attn_kernel(const float* __restrict__ q,
                 const float* __restrict__ k,
                 const float* __restrict__ v,
                 const int*   __restrict__ mask,
                 float* __restrict__ ctx)
{
    __shared__ float4 Ks[64][16];
    __shared__ float4 Vs[64][16];
    __shared__ int    mk[64];

    const int tid = threadIdx.x;
    const int bh  = blockIdx.y;
    const int b   = bh >> 4;       // / NHEAD
    const int h   = bh & 15;       // % NHEAD
    const int s   = blockIdx.x * 64 + tid;

    const float4* qp = (const float4*)(q + (size_t)(b * S_LEN + s) * D_DIM + h * DK_DIM);
    float4 qr[16];
#pragma unroll
    for (int i = 0; i < 16; i++) qr[i] = qp[i];

    float acc[64];
#pragma unroll
    for (int d = 0; d < 64; d++) acc[d] = 0.f;
    float mval = -1e30f, l = 0.f;

    for (int kt = 0; kt < S_LEN; kt += 64) {
        __syncthreads();
        const float4* kp = (const float4*)(k + (size_t)(b * S_LEN + kt + tid) * D_DIM + h * DK_DIM);
        const float4* vp = (const float4*)(v + (size_t)(b * S_LEN + kt + tid) * D_DIM + h * DK_DIM);
#pragma unroll
        for (int i = 0; i < 16; i++) { Ks[tid][i] = kp[i]; Vs[tid][i] = vp[i]; }
        mk[tid] = mask[b * S_LEN + kt + tid];
        __syncthreads();

        for (int j = 0; j < 64; j++) {
            float sc = 0.f;
#pragma unroll
            for (int i = 0; i < 16; i++) {
                float4 kk = Ks[j][i];
                sc += qr[i].x * kk.x + qr[i].y * kk.y + qr[i].z * kk.z + qr[i].w * kk.w;
            }
            sc *= 0.125f;                      // 1/sqrt(64)
            if (mk[j] == 0) sc = -1e9f;

            if (sc > mval) {
                float corr = __expf(mval - sc);
                l *= corr;
#pragma unroll
                for (int d = 0; d < 64; d++) acc[d] *= corr;
                mval = sc;
            }
            float p = __expf(sc - mval);
            l += p;
#pragma unroll
            for (int i = 0; i < 16; i++) {
                float4 vv = Vs[j][i];
                acc[i * 4 + 0] += p * vv.x;
                acc[i * 4 + 1] += p * vv.y;
                acc[i * 4 + 2] += p * vv.z;
                acc[i * 4 + 3] += p * vv.w;
            }
        }
    }

    const float inv = 1.f / l;
    float4* op = (float4*)(ctx + (size_t)(b * S_LEN + s) * D_DIM + h * DK_DIM);
#pragma unroll
    for (int i = 0; i < 16; i++) {
        float4 o;
        o.x = acc[i * 4 + 0] * inv;
        o.y = acc[i * 4 + 1] * inv;
        o.z = acc[i * 4 + 2] * inv;
        o.w = acc[i * 4 + 3] * inv;
        op[i] = o;
    }
}

// ---------------- LayerNorm (unbiased std, eps added to STD) -------------
// out = g * (x - mean) / (std + eps) + be,  std = sqrt(sum((x-mean)^2)/(D-1))
__global__ __launch_bounds__(256)
void ln_kernel(const float* __restrict__ x,
               const float* __restrict__ g,
               const float* __restrict__ be,
               float* __restrict__ out)
{
    __shared__ float red[256];
    const int row = blockIdx.x;
    const int tid = threadIdx.x;

    float4 xv = ((const float4*)(x + (size_t)row * D_DIM))[tid];
    red[tid] = xv.x + xv.y + xv.z + xv.w;
    __syncthreads();
    for (int off = 128; off > 0; off >>= 1) {
        if (tid < off) red[tid] += red[tid + off];
        __syncthreads();
    }
    const float mean = red[0] * (1.f / (float)D_DIM);
    __syncthreads();

    float dx0 = xv.x - mean, dx1 = xv.y - mean, dx2 = xv.z - mean, dx3 = xv.w - mean;
    red[tid] = dx0 * dx0 + dx1 * dx1 + dx2 * dx2 + dx3 * dx3;
    __syncthreads();
    for (int off = 128; off > 0; off >>= 1) {
        if (tid < off) red[tid] += red[tid + off];
        __syncthreads();
    }
    const float var  = red[0] * (1.f / (float)(D_DIM - 1));
    const float istd = 1.f / (sqrtf(var) + 1e-6f);

    float4 gv  = ((const float4*)g)[tid];
    float4 bev = ((const float4*)be)[tid];
    float4 o;
    o.x = gv.x * dx0 * istd + bev.x;
    o.y = gv.y * dx1 * istd + bev.y;
    o.z = gv.z * dx2 * istd + bev.z;
    o.w = gv.w * dx3 * istd + bev.w;
    ((float4*)(out + (size_t)row * D_DIM))[tid] = o;
}

// ---------------- host launcher -----------------------------------------
extern "C" void kernel_launch(void* const* d_in, const int* in_sizes, int n_in,
                              void* d_out, int out_size)
{
    const float* x    = (const float*)d_in[0];
    const int*   mask = (const int*)  d_in[1];
    const float* Wq   = (const float*)d_in[2];
    const float* bq   = (const float*)d_in[3];
    const float* Wk   = (const float*)d_in[4];
    const float* bk   = (const float*)d_in[5];
    const float* Wv   = (const float*)d_in[6];
    const float* bv   = (const float*)d_in[7];
    const float* Wo   = (const float*)d_in[8];
    const float* bo   = (const float*)d_in[9];
    const float* W1   = (const float*)d_in[10];
    const float* b1   = (const float*)d_in[11];
    const float* W2   = (const float*)d_in[12];
    const float* b2   = (const float*)d_in[13];
    const float* g1   = (const float*)d_in[14];
    const float* be1  = (const float*)d_in[15];
    const float* g2   = (const float*)d_in[16];
    const float* be2  = (const float*)d_in[17];
    float* out = (float*)d_out;

    float *q, *k, *v, *ctx, *y1, *x1, *h, *y2;
    cudaGetSymbolAddress((void**)&q,   g_q);
    cudaGetSymbolAddress((void**)&k,   g_k);
    cudaGetSymbolAddress((void**)&v,   g_v);
    cudaGetSymbolAddress((void**)&ctx, g_ctx);
    cudaGetSymbolAddress((void**)&y1,  g_y1);
    cudaGetSymbolAddress((void**)&x1,  g_x1);
    cudaGetSymbolAddress((void**)&h,   g_h);
    cudaGetSymbolAddress((void**)&y2,  g_y2);

    const dim3 gProj(D_DIM / 128, M_ROWS / 128);   // (8, 64)
    const dim3 gFfn1(DFF_D / 128, M_ROWS / 128);   // (32, 64)

    // QKV projections
    sgemm_bias<false, false><<<gProj, 256>>>(x, Wq, bq, nullptr, q, M_ROWS, D_DIM, D_DIM);
    sgemm_bias<false, false><<<gProj, 256>>>(x, Wk, bk, nullptr, k, M_ROWS, D_DIM, D_DIM);
    sgemm_bias<false, false><<<gProj, 256>>>(x, Wv, bv, nullptr, v, M_ROWS, D_DIM, D_DIM);

    // Attention
    attn_kernel<<<dim3(S_LEN / 64, B_SZ * NHEAD), 64>>>(q, k, v, mask, ctx);

    // Output projection + residual
    sgemm_bias<false, true><<<gProj, 256>>>(ctx, Wo, bo, x, y1, M_ROWS, D_DIM, D_DIM);
    ln_kernel<<<M_ROWS, 256>>>(y1, g1, be1, x1);

    // FFN
    sgemm_bias<true, false><<<gFfn1, 256>>>(x1, W1, b1, nullptr, h, M_ROWS, DFF_D, D_DIM);
    sgemm_bias<false, true><<<gProj, 256>>>(h, W2, b2, x1, y2, M_ROWS, D_DIM, DFF_D);
    ln_kernel<<<M_ROWS, 256>>>(y2, g2, be2, out);
}

// round 3
// speedup vs baseline: 1.3905x; 1.3905x over previous
#include <cuda_runtime.h>
#include <cuda_bf16.h>
#include <cstdint>
#include <math.h>

// Problem dims (fixed by the reference)
#define B_SZ   4
#define S_LEN  2048
#define D_DIM  1024
#define NHEAD  16
#define DK_DIM 64
#define DFF_D  4096
#define M_ROWS 8192   // B*S

// ---------------- scratch (static __device__ arrays; no allocation) -------
__device__ float g_q  [M_ROWS * D_DIM];
__device__ float g_k  [M_ROWS * D_DIM];
__device__ float g_v  [M_ROWS * D_DIM];
__device__ float g_ctx[M_ROWS * D_DIM];
__device__ float g_y1 [M_ROWS * D_DIM];
__device__ float g_x1 [M_ROWS * D_DIM];
__device__ float g_h  [M_ROWS * DFF_D];
__device__ float g_y2 [M_ROWS * D_DIM];

// ======================= helpers ==========================================
__device__ __forceinline__ uint32_t smem_u32(const void* p) {
    uint32_t a;
    asm("{ .reg .u64 t; cvta.to.shared.u64 t, %1; cvt.u32.u64 %0, t; }" : "=r"(a) : "l"(p));
    return a;
}
__device__ __forceinline__ uint32_t sw128(uint32_t off) { return off ^ ((off >> 3) & 0x70); }

__device__ __forceinline__ void ldsm_x4(uint32_t& r0, uint32_t& r1, uint32_t& r2, uint32_t& r3,
                                        uint32_t addr) {
    asm volatile("ldmatrix.sync.aligned.m8n8.x4.shared.b16 {%0,%1,%2,%3}, [%4];"
                 : "=r"(r0), "=r"(r1), "=r"(r2), "=r"(r3) : "r"(addr));
}
__device__ __forceinline__ void mma_bf16(float* d, uint32_t a0, uint32_t a1, uint32_t a2,
                                         uint32_t a3, uint32_t b0, uint32_t b1) {
    asm volatile(
        "mma.sync.aligned.m16n8k16.row.col.f32.bf16.bf16.f32 "
        "{%0,%1,%2,%3}, {%4,%5,%6,%7}, {%8,%9}, {%0,%1,%2,%3};"
        : "+f"(d[0]), "+f"(d[1]), "+f"(d[2]), "+f"(d[3])
        : "r"(a0), "r"(a1), "r"(a2), "r"(a3), "r"(b0), "r"(b1));
}

// convert 8 fp32 -> 8 hi bf16 + 8 lo bf16 (packed pairs, memory order)
__device__ __forceinline__ void cvt8(const float4 v0, const float4 v1,
                                     uint32_t h[4], uint32_t l[4]) {
    const float4 vv[2] = {v0, v1};
#pragma unroll
    for (int p = 0; p < 2; p++) {
        float4 v = vv[p];
        uint32_t h0, h1;
        asm("cvt.rn.bf16x2.f32 %0, %1, %2;" : "=r"(h0) : "f"(v.y), "f"(v.x));
        asm("cvt.rn.bf16x2.f32 %0, %1, %2;" : "=r"(h1) : "f"(v.w), "f"(v.z));
        float r0 = v.x - __uint_as_float(h0 << 16);
        float r1 = v.y - __uint_as_float(h0 & 0xffff0000u);
        float r2 = v.z - __uint_as_float(h1 << 16);
        float r3 = v.w - __uint_as_float(h1 & 0xffff0000u);
        uint32_t l0, l1;
        asm("cvt.rn.bf16x2.f32 %0, %1, %2;" : "=r"(l0) : "f"(r1), "f"(r0));
        asm("cvt.rn.bf16x2.f32 %0, %1, %2;" : "=r"(l1) : "f"(r3), "f"(r2));
        h[2 * p] = h0; h[2 * p + 1] = h1;
        l[2 * p] = l0; l[2 * p + 1] = l1;
    }
}

// ======== HMMA split-bf16 GEMM: C[M,N] = A[M,K] @ W[N,K]^T + bias ========
// CTA tile 128x128, 8 warps (4m x 2n), warp tile 32x64.
// K chunk = 64 bf16 (128B SW128 rows). Double-buffered smem (2 x 64KB).
// Per smem tile: AHI(16K) ALO(16K) BHI(16K) BLO(16K).
#define TB_AHI 0
#define TB_ALO 16384
#define TB_BHI 32768
#define TB_BLO 49152
#define TB_SZ  65536
#define SM_TOTAL (2 * TB_SZ)

template<bool RELU, bool RES>
__global__ __launch_bounds__(256)
void hmma_gemm(const float* __restrict__ A, const float* __restrict__ W,
               const float* __restrict__ bias, const float* __restrict__ Rp,
               float* __restrict__ C, int M, int N, int K)
{
    extern __shared__ __align__(1024) char smem[];
    const uint32_t sb = smem_u32(smem);
    const int tid  = threadIdx.x;
    const int lane = tid & 31;
    const int wid  = tid >> 5;
    const int wm   = wid & 3;    // warp m-tile (0..3), 32 rows
    const int wn   = wid >> 2;   // warp n-tile (0..1), 64 cols
    const int bx = blockIdx.x, by = blockIdx.y;

    // --- loader mapping: thread -> (row, 32-col half) of 128x64 fp32 chunk
    const int lrow  = tid >> 1;
    const int lcolh = (tid & 1) * 32;
    const float* Ap = A + (size_t)(by * 128 + lrow) * K + lcolh;
    const float* Wp = W + (size_t)(bx * 128 + lrow) * K + lcolh;
    uint32_t soff[4];
#pragma unroll
    for (int u = 0; u < 4; u++) soff[u] = sw128((uint32_t)(lrow * 128 + (lcolh + u * 8) * 2));

    // --- ldmatrix byte-offset bases (pre-swizzle) ---
    // A x4 tiles: (m0-7,k0-7),(m8-15,k0-7),(m0-7,k8-15),(m8-15,k8-15)
    uint32_t aoff[2];
    {
        const int m  = wm * 32 + (lane & 7) + 8 * ((lane >> 3) & 1);
        const int ak = (lane >> 4) * 16;   // bytes
        aoff[0] = (uint32_t)(m * 128 + ak);
        aoff[1] = aoff[0] + 16 * 128;
    }
    // B x4 tiles: (n0-7,k0-7),(n0-7,k8-15),(n8-15,k0-7),(n8-15,k8-15)
    uint32_t boff[4];
    {
        const int bk = ((lane >> 3) & 1) * 16;
#pragma unroll
        for (int jg = 0; jg < 4; jg++) {
            const int n = wn * 64 + jg * 16 + (lane & 7) + 8 * (lane >> 4);
            boff[jg] = (uint32_t)(n * 128 + bk);
        }
    }

    float acc[2][8][4];
#pragma unroll
    for (int i = 0; i < 2; i++)
#pragma unroll
        for (int j = 0; j < 8; j++)
#pragma unroll
            for (int r = 0; r < 4; r++) acc[i][j][r] = 0.f;

    const int nchunk = K >> 6;
    float4 av[8], wv[8];
#pragma unroll
    for (int u = 0; u < 8; u++) { av[u] = *(const float4*)(Ap + u * 4); }
#pragma unroll
    for (int u = 0; u < 8; u++) { wv[u] = *(const float4*)(Wp + u * 4); }

    for (int c = 0; c < nchunk; c++) {
        char* buf = smem + (c & 1) * TB_SZ;
        const uint32_t bufb = sb + (c & 1) * TB_SZ;

        // convert + store current chunk
#pragma unroll
        for (int u = 0; u < 4; u++) {
            uint32_t h[4], l[4];
            cvt8(av[2 * u], av[2 * u + 1], h, l);
            *(uint4*)(buf + TB_AHI + soff[u]) = make_uint4(h[0], h[1], h[2], h[3]);
            *(uint4*)(buf + TB_ALO + soff[u]) = make_uint4(l[0], l[1], l[2], l[3]);
            cvt8(wv[2 * u], wv[2 * u + 1], h, l);
            *(uint4*)(buf + TB_BHI + soff[u]) = make_uint4(h[0], h[1], h[2], h[3]);
            *(uint4*)(buf + TB_BLO + soff[u]) = make_uint4(l[0], l[1], l[2], l[3]);
        }
        __syncthreads();

        // prefetch next chunk (hidden under the MMAs below)
        if (c + 1 < nchunk) {
            const float* Ap2 = Ap + (c + 1) * 64;
            const float* Wp2 = Wp + (c + 1) * 64;
#pragma unroll
            for (int u = 0; u < 8; u++) av[u] = *(const float4*)(Ap2 + u * 4);
#pragma unroll
            for (int u = 0; u < 8; u++) wv[u] = *(const float4*)(Wp2 + u * 4);
        }

        // MMA over 4 k-steps of 16
#pragma unroll
        for (int ks = 0; ks < 4; ks++) {
            const uint32_t o = ks * 32;
            uint32_t ah0[4], ah1[4], al0[4], al1[4];
            ldsm_x4(ah0[0], ah0[1], ah0[2], ah0[3], bufb + TB_AHI + sw128(aoff[0] + o));
            ldsm_x4(ah1[0], ah1[1], ah1[2], ah1[3], bufb + TB_AHI + sw128(aoff[1] + o));
            ldsm_x4(al0[0], al0[1], al0[2], al0[3], bufb + TB_ALO + sw128(aoff[0] + o));
            ldsm_x4(al1[0], al1[1], al1[2], al1[3], bufb + TB_ALO + sw128(aoff[1] + o));
#pragma unroll
            for (int jg = 0; jg < 4; jg++) {
                uint32_t bh[4], bl[4];
                ldsm_x4(bh[0], bh[1], bh[2], bh[3], bufb + TB_BHI + sw128(boff[jg] + o));
                ldsm_x4(bl[0], bl[1], bl[2], bl[3], bufb + TB_BLO + sw128(boff[jg] + o));
                const int j0 = 2 * jg, j1 = 2 * jg + 1;
                // hi*hi
                mma_bf16(acc[0][j0], ah0[0], ah0[1], ah0[2], ah0[3], bh[0], bh[1]);
                mma_bf16(acc[0][j1], ah0[0], ah0[1], ah0[2], ah0[3], bh[2], bh[3]);
                mma_bf16(acc[1][j0], ah1[0], ah1[1], ah1[2], ah1[3], bh[0], bh[1]);
                mma_bf16(acc[1][j1], ah1[0], ah1[1], ah1[2], ah1[3], bh[2], bh[3]);
                // hi*lo
                mma_bf16(acc[0][j0], ah0[0], ah0[1], ah0[2], ah0[3], bl[0], bl[1]);
                mma_bf16(acc[0][j1], ah0[0], ah0[1], ah0[2], ah0[3], bl[2], bl[3]);
                mma_bf16(acc[1][j0], ah1[0], ah1[1], ah1[2], ah1[3], bl[0], bl[1]);
                mma_bf16(acc[1][j1], ah1[0], ah1[1], ah1[2], ah1[3], bl[2], bl[3]);
                // lo*hi
                mma_bf16(acc[0][j0], al0[0], al0[1], al0[2], al0[3], bh[0], bh[1]);
                mma_bf16(acc[0][j1], al0[0], al0[1], al0[2], al0[3], bh[2], bh[3]);
                mma_bf16(acc[1][j0], al1[0], al1[1], al1[2], al1[3], bh[0], bh[1]);
                mma_bf16(acc[1][j1], al1[0], al1[1], al1[2], al1[3], bh[2], bh[3]);
            }
        }
    }

    // --- epilogue: fragment layout row = l/4 (+8), col = (l&3)*2 ---
    const int rbase = by * 128 + wm * 32 + (lane >> 2);
    const int cbase = bx * 128 + wn * 64 + (lane & 3) * 2;
#pragma unroll
    for (int i = 0; i < 2; i++) {
#pragma unroll
        for (int j = 0; j < 8; j++) {
            const int r0 = rbase + i * 16;
            const int cc = cbase + j * 8;
            const float2 bv = *(const float2*)&bias[cc];
            float2 v0, v1;
            v0.x = acc[i][j][0] + bv.x;  v0.y = acc[i][j][1] + bv.y;
            v1.x = acc[i][j][2] + bv.x;  v1.y = acc[i][j][3] + bv.y;
            if (RES) {
                float2 q0 = *(const float2*)&Rp[(size_t)r0 * N + cc];
                float2 q1 = *(const float2*)&Rp[(size_t)(r0 + 8) * N + cc];
                v0.x += q0.x; v0.y += q0.y; v1.x += q1.x; v1.y += q1.y;
            }
            if (RELU) {
                v0.x = fmaxf(v0.x, 0.f); v0.y = fmaxf(v0.y, 0.f);
                v1.x = fmaxf(v1.x, 0.f); v1.y = fmaxf(v1.y, 0.f);
            }
            *(float2*)&C[(size_t)r0 * N + cc]       = v0;
            *(float2*)&C[(size_t)(r0 + 8) * N + cc] = v1;
        }
    }
}

// ---------------- Flash-style attention (ILP-optimized) ------------------
__global__ __launch_bounds__(64)
void attn_kernel(const float* __restrict__ q,
                 const float* __restrict__ k,
                 const float* __restrict__ v,
                 const int*   __restrict__ mask,
                 float* __restrict__ ctx)
{
    __shared__ float4 Ks[64][16];
    __shared__ float4 Vs[64][16];
    __shared__ int    mk[64];

    const int tid = threadIdx.x;
    const int bh  = blockIdx.y;
    const int b   = bh >> 4;
    const int h   = bh & 15;
    const int s   = blockIdx.x * 64 + tid;

    const float4* qp = (const float4*)(q + (size_t)(b * S_LEN + s) * D_DIM + h * DK_DIM);
    float4 qr[16];
#pragma unroll
    for (int i = 0; i < 16; i++) qr[i] = qp[i];

    float acc[64];
#pragma unroll
    for (int d = 0; d < 64; d++) acc[d] = 0.f;
    float mval = -1e30f, l = 0.f;

    for (int kt = 0; kt < S_LEN; kt += 64) {
        __syncthreads();
        const float4* kp = (const float4*)(k + (size_t)(b * S_LEN + kt + tid) * D_DIM + h * DK_DIM);
        const float4* vp = (const float4*)(v + (size_t)(b * S_LEN + kt + tid) * D_DIM + h * DK_DIM);
#pragma unroll
        for (int i = 0; i < 16; i++) { Ks[tid][i] = kp[i]; Vs[tid][i] = vp[i]; }
        mk[tid] = mask[b * S_LEN + kt + tid];
        __syncthreads();

        for (int j = 0; j < 64; j += 4) {
            float sc[4];
#pragma unroll
            for (int jj = 0; jj < 4; jj++) {
                float a0 = 0.f, a1 = 0.f, a2 = 0.f, a3 = 0.f;
#pragma unroll
                for (int i = 0; i < 16; i++) {
                    float4 kk = Ks[j + jj][i];
                    a0 += qr[i].x * kk.x;
                    a1 += qr[i].y * kk.y;
                    a2 += qr[i].z * kk.z;
                    a3 += qr[i].w * kk.w;
                }
                float t = ((a0 + a1) + (a2 + a3)) * 0.125f;
                sc[jj] = (mk[j + jj] == 0) ? -1e9f : t;
            }
            float mnew = fmaxf(fmaxf(sc[0], sc[1]), fmaxf(sc[2], sc[3]));
            if (mnew > mval) {
                const float corr = __expf(mval - mnew);
                l *= corr;
#pragma unroll
                for (int d = 0; d < 64; d++) acc[d] *= corr;
                mval = mnew;
            }
            const float p0 = __expf(sc[0] - mval);
            const float p1 = __expf(sc[1] - mval);
            const float p2 = __expf(sc[2] - mval);
            const float p3 = __expf(sc[3] - mval);
            l += (p0 + p1) + (p2 + p3);
#pragma unroll
            for (int i = 0; i < 16; i++) {
                float4 v0 = Vs[j][i], v1 = Vs[j + 1][i], v2 = Vs[j + 2][i], v3 = Vs[j + 3][i];
                acc[4 * i + 0] += p0 * v0.x; acc[4 * i + 0] += p1 * v1.x;
                acc[4 * i + 0] += p2 * v2.x; acc[4 * i + 0] += p3 * v3.x;
                acc[4 * i + 1] += p0 * v0.y; acc[4 * i + 1] += p1 * v1.y;
                acc[4 * i + 1] += p2 * v2.y; acc[4 * i + 1] += p3 * v3.y;
                acc[4 * i + 2] += p0 * v0.z; acc[4 * i + 2] += p1 * v1.z;
                acc[4 * i + 2] += p2 * v2.z; acc[4 * i + 2] += p3 * v3.z;
                acc[4 * i + 3] += p0 * v0.w; acc[4 * i + 3] += p1 * v1.w;
                acc[4 * i + 3] += p2 * v2.w; acc[4 * i + 3] += p3 * v3.w;
            }
        }
    }

    const float inv = 1.f / l;
    float4* op = (float4*)(ctx + (size_t)(b * S_LEN + s) * D_DIM + h * DK_DIM);
#pragma unroll
    for (int i = 0; i < 16; i++) {
        float4 o;
        o.x = acc[i * 4 + 0] * inv;
        o.y = acc[i * 4 + 1] * inv;
        o.z = acc[i * 4 + 2] * inv;
        o.w = acc[i * 4 + 3] * inv;
        op[i] = o;
    }
}

// ---------------- LayerNorm (unbiased std, eps added to STD) -------------
__global__ __launch_bounds__(256)
void ln_kernel(const float* __restrict__ x,
               const float* __restrict__ g,
               const float* __restrict__ be,
               float* __restrict__ out)
{
    __shared__ float red[256];
    const int row = blockIdx.x;
    const int tid = threadIdx.x;

    float4 xv = ((const float4*)(x + (size_t)row * D_DIM))[tid];
    red[tid] = xv.x + xv.y + xv.z + xv.w;
    __syncthreads();
    for (int off = 128; off > 0; off >>= 1) {
        if (tid < off) red[tid] += red[tid + off];
        __syncthreads();
    }
    const float mean = red[0] * (1.f / (float)D_DIM);
    __syncthreads();

    float dx0 = xv.x - mean, dx1 = xv.y - mean, dx2 = xv.z - mean, dx3 = xv.w - mean;
    red[tid] = dx0 * dx0 + dx1 * dx1 + dx2 * dx2 + dx3 * dx3;
    __syncthreads();
    for (int off = 128; off > 0; off >>= 1) {
        if (tid < off) red[tid] += red[tid + off];
        __syncthreads();
    }
    const float var  = red[0] * (1.f / (float)(D_DIM - 1));
    const float istd = 1.f / (sqrtf(var) + 1e-6f);

    float4 gv  = ((const float4*)g)[tid];
    float4 bev = ((const float4*)be)[tid];
    float4 o;
    o.x = gv.x * dx0 * istd + bev.x;
    o.y = gv.y * dx1 * istd + bev.y;
    o.z = gv.z * dx2 * istd + bev.z;
    o.w = gv.w * dx3 * istd + bev.w;
    ((float4*)(out + (size_t)row * D_DIM))[tid] = o;
}

// ---------------- host launcher -----------------------------------------
extern "C" void kernel_launch(void* const* d_in, const int* in_sizes, int n_in,
                              void* d_out, int out_size)
{
    const float* x    = (const float*)d_in[0];
    const int*   mask = (const int*)  d_in[1];
    const float* Wq   = (const float*)d_in[2];
    const float* bq   = (const float*)d_in[3];
    const float* Wk   = (const float*)d_in[4];
    const float* bk   = (const float*)d_in[5];
    const float* Wv   = (const float*)d_in[6];
    const float* bv   = (const float*)d_in[7];
    const float* Wo   = (const float*)d_in[8];
    const float* bo   = (const float*)d_in[9];
    const float* W1   = (const float*)d_in[10];
    const float* b1   = (const float*)d_in[11];
    const float* W2   = (const float*)d_in[12];
    const float* b2   = (const float*)d_in[13];
    const float* g1   = (const float*)d_in[14];
    const float* be1  = (const float*)d_in[15];
    const float* g2   = (const float*)d_in[16];
    const float* be2  = (const float*)d_in[17];
    float* out = (float*)d_out;

    float *q, *k, *v, *ctx, *y1, *x1, *h, *y2;
    cudaGetSymbolAddress((void**)&q,   g_q);
    cudaGetSymbolAddress((void**)&k,   g_k);
    cudaGetSymbolAddress((void**)&v,   g_v);
    cudaGetSymbolAddress((void**)&ctx, g_ctx);
    cudaGetSymbolAddress((void**)&y1,  g_y1);
    cudaGetSymbolAddress((void**)&x1,  g_x1);
    cudaGetSymbolAddress((void**)&h,   g_h);
    cudaGetSymbolAddress((void**)&y2,  g_y2);

    cudaFuncSetAttribute(hmma_gemm<false, false>, cudaFuncAttributeMaxDynamicSharedMemorySize, SM_TOTAL);
    cudaFuncSetAttribute(hmma_gemm<false, true >, cudaFuncAttributeMaxDynamicSharedMemorySize, SM_TOTAL);
    cudaFuncSetAttribute(hmma_gemm<true,  false>, cudaFuncAttributeMaxDynamicSharedMemorySize, SM_TOTAL);

    const dim3 gProj(D_DIM / 128, M_ROWS / 128);   // (8, 64)
    const dim3 gFfn1(DFF_D / 128, M_ROWS / 128);   // (32, 64)

    // QKV projections
    hmma_gemm<false, false><<<gProj, 256, SM_TOTAL>>>(x, Wq, bq, nullptr, q, M_ROWS, D_DIM, D_DIM);
    hmma_gemm<false, false><<<gProj, 256, SM_TOTAL>>>(x, Wk, bk, nullptr, k, M_ROWS, D_DIM, D_DIM);
    hmma_gemm<false, false><<<gProj, 256, SM_TOTAL>>>(x, Wv, bv, nullptr, v, M_ROWS, D_DIM, D_DIM);

    // Attention
    attn_kernel<<<dim3(S_LEN / 64, B_SZ * NHEAD), 64>>>(q, k, v, mask, ctx);

    // Output projection + residual, then LN1
    hmma_gemm<false, true><<<gProj, 256, SM_TOTAL>>>(ctx, Wo, bo, x, y1, M_ROWS, D_DIM, D_DIM);
    ln_kernel<<<M_ROWS, 256>>>(y1, g1, be1, x1);

    // FFN
    hmma_gemm<true,  false><<<gFfn1, 256, SM_TOTAL>>>(x1, W1, b1, nullptr, h, M_ROWS, DFF_D, D_DIM);
    hmma_gemm<false, true><<<gProj, 256, SM_TOTAL>>>(h, W2, b2, x1, y2, M_ROWS, D_DIM, DFF_D);
    ln_kernel<<<M_ROWS, 256>>>(y2, g2, be2, out);
}

// round 4
// speedup vs baseline: 3.1670x; 2.2776x over previous
#include <cuda_runtime.h>
#include <cuda_bf16.h>
#include <cstdint>
#include <math.h>

// Problem dims (fixed)
#define B_SZ   4
#define S_LEN  2048
#define D_DIM  1024
#define NHEAD  16
#define DFF_D  4096
#define M_ROWS 8192   // B*S

// ---------------- scratch (static __device__; no allocation) --------------
__device__ __nv_bfloat16 g_xhi [M_ROWS * D_DIM], g_xlo [M_ROWS * D_DIM];
__device__ __nv_bfloat16 g_wqkvhi[3 * D_DIM * D_DIM], g_wqkvlo[3 * D_DIM * D_DIM];
__device__ __nv_bfloat16 g_wohi[D_DIM * D_DIM], g_wolo[D_DIM * D_DIM];
__device__ __nv_bfloat16 g_w1hi[DFF_D * D_DIM], g_w1lo[DFF_D * D_DIM];
__device__ __nv_bfloat16 g_w2hi[D_DIM * DFF_D], g_w2lo[D_DIM * DFF_D];
__device__ float         g_bqkv[3 * D_DIM];
__device__ __nv_bfloat16 g_qkvhi[(size_t)M_ROWS * 3 * D_DIM], g_qkvlo[(size_t)M_ROWS * 3 * D_DIM];
__device__ __nv_bfloat16 g_vthi[M_ROWS * D_DIM], g_vtlo[M_ROWS * D_DIM];
__device__ __nv_bfloat16 g_ctxhi[M_ROWS * D_DIM], g_ctxlo[M_ROWS * D_DIM];
__device__ float         g_y1 [M_ROWS * D_DIM], g_x1f[M_ROWS * D_DIM], g_y2[M_ROWS * D_DIM];
__device__ __nv_bfloat16 g_x1hi[M_ROWS * D_DIM], g_x1lo[M_ROWS * D_DIM];
__device__ __nv_bfloat16 g_hhi[(size_t)M_ROWS * DFF_D], g_hlo[(size_t)M_ROWS * DFF_D];

// ======================= helpers ==========================================
__device__ __forceinline__ uint32_t smem_u32(const void* p) {
    uint32_t a;
    asm("{ .reg .u64 t; cvta.to.shared.u64 t, %1; cvt.u32.u64 %0, t; }" : "=r"(a) : "l"(p));
    return a;
}
__device__ __forceinline__ uint32_t sw128(uint32_t off) { return off ^ ((off >> 3) & 0x70); }

__device__ __forceinline__ void ldsm_x4(uint32_t& r0, uint32_t& r1, uint32_t& r2, uint32_t& r3,
                                        uint32_t addr) {
    asm volatile("ldmatrix.sync.aligned.m8n8.x4.shared.b16 {%0,%1,%2,%3}, [%4];"
                 : "=r"(r0), "=r"(r1), "=r"(r2), "=r"(r3) : "r"(addr));
}
__device__ __forceinline__ void mma_bf16(float* d, uint32_t a0, uint32_t a1, uint32_t a2,
                                         uint32_t a3, uint32_t b0, uint32_t b1) {
    asm volatile(
        "mma.sync.aligned.m16n8k16.row.col.f32.bf16.bf16.f32 "
        "{%0,%1,%2,%3}, {%4,%5,%6,%7}, {%8,%9}, {%0,%1,%2,%3};"
        : "+f"(d[0]), "+f"(d[1]), "+f"(d[2]), "+f"(d[3])
        : "r"(a0), "r"(a1), "r"(a2), "r"(a3), "r"(b0), "r"(b1));
}
// split pair (a=elem0/lo, b=elem1/hi) into hi/lo bf16x2
__device__ __forceinline__ void split2(float a, float b, uint32_t& hi, uint32_t& lo) {
    uint32_t h;
    asm("cvt.rn.bf16x2.f32 %0, %1, %2;" : "=r"(h) : "f"(b), "f"(a));
    float ra = a - __uint_as_float(h << 16);
    float rb = b - __uint_as_float(h & 0xffff0000u);
    uint32_t l;
    asm("cvt.rn.bf16x2.f32 %0, %1, %2;" : "=r"(l) : "f"(rb), "f"(ra));
    hi = h; lo = l;
}

#define CP_ASYNC16(dst, src) \
    asm volatile("cp.async.cg.shared.global [%0], [%1], 16;" :: "r"(dst), "l"(src))
#define CP_COMMIT asm volatile("cp.async.commit_group;" ::: "memory")
#define CP_WAIT1  asm volatile("cp.async.wait_group 1;" ::: "memory")
#define CP_WAIT0  asm volatile("cp.async.wait_group 0;" ::: "memory")

// ---------------- fp32 -> split bf16 conversion ---------------------------
__global__ void convsplit(const float* __restrict__ src, __nv_bfloat16* __restrict__ hi,
                          __nv_bfloat16* __restrict__ lo, int n4)
{
    int i = blockIdx.x * blockDim.x + threadIdx.x;
    if (i >= n4) return;
    float4 v = ((const float4*)src)[i];
    uint32_t h0, l0, h1, l1;
    split2(v.x, v.y, h0, l0);
    split2(v.z, v.w, h1, l1);
    ((uint2*)hi)[i] = make_uint2(h0, h1);
    ((uint2*)lo)[i] = make_uint2(l0, l1);
}
__global__ void concat3(const float* a, const float* b, const float* c, float* out)
{
    int i = blockIdx.x * blockDim.x + threadIdx.x;   // 3072
    out[i] = (i < 1024) ? a[i] : ((i < 2048) ? b[i - 1024] : c[i - 2048]);
}

// ========== HMMA GEMM on pre-split inputs: C = A @ B^T + bias =============
// A[M,K], B[N,K] as hi/lo bf16. Tile 128x128, K-chunk 64, 2-stage cp.async.
// MODE 0: fp32 out (+RES). MODE 1: split bf16 out (+RELU).
#define ST_A 0
#define ST_AL 16384
#define ST_B 32768
#define ST_BL 49152
#define ST_SZ 65536
#define GEMM_SMEM (2 * ST_SZ)

template<int MODE, bool RELU, bool RES>
__global__ __launch_bounds__(256)
void hmma_gemm2(const __nv_bfloat16* __restrict__ Ahi, const __nv_bfloat16* __restrict__ Alo,
                const __nv_bfloat16* __restrict__ Bhi, const __nv_bfloat16* __restrict__ Blo,
                const float* __restrict__ bias, const float* __restrict__ Rp,
                float* __restrict__ Cf, __nv_bfloat16* __restrict__ Chi,
                __nv_bfloat16* __restrict__ Clo, int M, int N, int K)
{
    extern __shared__ __align__(1024) char smem[];
    const uint32_t sb = smem_u32(smem);
    const int tid  = threadIdx.x;
    const int lane = tid & 31;
    const int wid  = tid >> 5;
    const int wm   = wid & 3;
    const int wn   = wid >> 2;
    const int bx = blockIdx.x, by = blockIdx.y;

    // loader mapping: thread -> row (0..127), 4 of 8 16B-chunks
    const int lrow = tid >> 1;
    const int lc4  = (tid & 1) * 4;
    const __nv_bfloat16* src0 = Ahi + (size_t)(by * 128 + lrow) * K;
    const __nv_bfloat16* src1 = Alo + (size_t)(by * 128 + lrow) * K;
    const __nv_bfloat16* src2 = Bhi + (size_t)(bx * 128 + lrow) * K;
    const __nv_bfloat16* src3 = Blo + (size_t)(bx * 128 + lrow) * K;
    uint32_t dsw[4];
#pragma unroll
    for (int ch = 0; ch < 4; ch++) dsw[ch] = sw128((uint32_t)(lrow * 128 + (lc4 + ch) * 16));

    const int nchunk = K >> 6;
    auto issue = [&](int c) {
        const uint32_t stg = sb + (c & 1) * ST_SZ;
        const int ko = c * 64 + lc4 * 8;
#pragma unroll
        for (int ch = 0; ch < 4; ch++) {
            CP_ASYNC16(stg + ST_A  + dsw[ch], src0 + ko + ch * 8);
            CP_ASYNC16(stg + ST_AL + dsw[ch], src1 + ko + ch * 8);
            CP_ASYNC16(stg + ST_B  + dsw[ch], src2 + ko + ch * 8);
            CP_ASYNC16(stg + ST_BL + dsw[ch], src3 + ko + ch * 8);
        }
        CP_COMMIT;
    };

    // ldmatrix offsets (verified layout)
    uint32_t aoff[2];
    {
        const int m  = wm * 32 + (lane & 7) + 8 * ((lane >> 3) & 1);
        const int ak = (lane >> 4) * 16;
        aoff[0] = (uint32_t)(m * 128 + ak);
        aoff[1] = aoff[0] + 16 * 128;
    }
    uint32_t boff[4];
    {
        const int bk = ((lane >> 3) & 1) * 16;
#pragma unroll
        for (int jg = 0; jg < 4; jg++) {
            const int n = wn * 64 + jg * 16 + (lane & 7) + 8 * (lane >> 4);
            boff[jg] = (uint32_t)(n * 128 + bk);
        }
    }

    float acc[2][8][4];
#pragma unroll
    for (int i = 0; i < 2; i++)
#pragma unroll
        for (int j = 0; j < 8; j++)
#pragma unroll
            for (int r = 0; r < 4; r++) acc[i][j][r] = 0.f;

    issue(0);
    if (nchunk > 1) issue(1);

    for (int c = 0; c < nchunk; c++) {
        if (c == nchunk - 1) { CP_WAIT0; } else { CP_WAIT1; }
        __syncthreads();
        const uint32_t bufb = sb + (c & 1) * ST_SZ;
#pragma unroll
        for (int ks = 0; ks < 4; ks++) {
            const uint32_t o = ks * 32;
            uint32_t ah0[4], ah1[4], al0[4], al1[4];
            ldsm_x4(ah0[0], ah0[1], ah0[2], ah0[3], bufb + ST_A  + sw128(aoff[0] + o));
            ldsm_x4(ah1[0], ah1[1], ah1[2], ah1[3], bufb + ST_A  + sw128(aoff[1] + o));
            ldsm_x4(al0[0], al0[1], al0[2], al0[3], bufb + ST_AL + sw128(aoff[0] + o));
            ldsm_x4(al1[0], al1[1], al1[2], al1[3], bufb + ST_AL + sw128(aoff[1] + o));
#pragma unroll
            for (int jg = 0; jg < 4; jg++) {
                uint32_t bh[4], bl[4];
                ldsm_x4(bh[0], bh[1], bh[2], bh[3], bufb + ST_B  + sw128(boff[jg] + o));
                ldsm_x4(bl[0], bl[1], bl[2], bl[3], bufb + ST_BL + sw128(boff[jg] + o));
                const int j0 = 2 * jg, j1 = 2 * jg + 1;
                mma_bf16(acc[0][j0], ah0[0], ah0[1], ah0[2], ah0[3], bh[0], bh[1]);
                mma_bf16(acc[0][j1], ah0[0], ah0[1], ah0[2], ah0[3], bh[2], bh[3]);
                mma_bf16(acc[1][j0], ah1[0], ah1[1], ah1[2], ah1[3], bh[0], bh[1]);
                mma_bf16(acc[1][j1], ah1[0], ah1[1], ah1[2], ah1[3], bh[2], bh[3]);
                mma_bf16(acc[0][j0], ah0[0], ah0[1], ah0[2], ah0[3], bl[0], bl[1]);
                mma_bf16(acc[0][j1], ah0[0], ah0[1], ah0[2], ah0[3], bl[2], bl[3]);
                mma_bf16(acc[1][j0], ah1[0], ah1[1], ah1[2], ah1[3], bl[0], bl[1]);
                mma_bf16(acc[1][j1], ah1[0], ah1[1], ah1[2], ah1[3], bl[2], bl[3]);
                mma_bf16(acc[0][j0], al0[0], al0[1], al0[2], al0[3], bh[0], bh[1]);
                mma_bf16(acc[0][j1], al0[0], al0[1], al0[2], al0[3], bh[2], bh[3]);
                mma_bf16(acc[1][j0], al1[0], al1[1], al1[2], al1[3], bh[0], bh[1]);
                mma_bf16(acc[1][j1], al1[0], al1[1], al1[2], al1[3], bh[2], bh[3]);
            }
        }
        __syncthreads();
        if (c + 2 < nchunk) issue(c + 2);
    }

    // epilogue: fragment row = lane>>2 (+8), col = (lane&3)*2
    const int rbase = by * 128 + wm * 32 + (lane >> 2);
    const int cbase = bx * 128 + wn * 64 + (lane & 3) * 2;
#pragma unroll
    for (int i = 0; i < 2; i++) {
#pragma unroll
        for (int j = 0; j < 8; j++) {
            const int r0 = rbase + i * 16;
            const int cc = cbase + j * 8;
            const float2 bv = *(const float2*)&bias[cc];
            float2 v0, v1;
            v0.x = acc[i][j][0] + bv.x;  v0.y = acc[i][j][1] + bv.y;
            v1.x = acc[i][j][2] + bv.x;  v1.y = acc[i][j][3] + bv.y;
            if (RES) {
                float2 q0 = *(const float2*)&Rp[(size_t)r0 * N + cc];
                float2 q1 = *(const float2*)&Rp[(size_t)(r0 + 8) * N + cc];
                v0.x += q0.x; v0.y += q0.y; v1.x += q1.x; v1.y += q1.y;
            }
            if (RELU) {
                v0.x = fmaxf(v0.x, 0.f); v0.y = fmaxf(v0.y, 0.f);
                v1.x = fmaxf(v1.x, 0.f); v1.y = fmaxf(v1.y, 0.f);
            }
            if (MODE == 0) {
                *(float2*)&Cf[(size_t)r0 * N + cc]       = v0;
                *(float2*)&Cf[(size_t)(r0 + 8) * N + cc] = v1;
            } else {
                uint32_t h, l;
                split2(v0.x, v0.y, h, l);
                *(uint32_t*)(Chi + (size_t)r0 * N + cc) = h;
                *(uint32_t*)(Clo + (size_t)r0 * N + cc) = l;
                split2(v1.x, v1.y, h, l);
                *(uint32_t*)(Chi + (size_t)(r0 + 8) * N + cc) = h;
                *(uint32_t*)(Clo + (size_t)(r0 + 8) * N + cc) = l;
            }
        }
    }
}

// ---------------- V transpose: qkv cols [2048..3072) -> vt[b,h,d,s] ------
__global__ __launch_bounds__(256)
void vtrans_kernel(const __nv_bfloat16* __restrict__ qkvhi,
                   const __nv_bfloat16* __restrict__ qkvlo,
                   __nv_bfloat16* __restrict__ vthi, __nv_bfloat16* __restrict__ vtlo)
{
    __shared__ uint16_t th[64][72];
    __shared__ uint16_t tl[64][72];
    const int tid = threadIdx.x;
    const int s0  = blockIdx.x * 64;
    const int bh  = blockIdx.y;
    const int b   = bh >> 4, h = bh & 15;

#pragma unroll
    for (int it = 0; it < 2; it++) {
        const int idx = it * 256 + tid;
        const int row = idx >> 3, ch = idx & 7;
        const size_t src = (size_t)(b * S_LEN + s0 + row) * 3072 + 2048 + h * 64 + ch * 8;
        *(uint4*)&th[row][ch * 8] = *(const uint4*)(qkvhi + src);
        *(uint4*)&tl[row][ch * 8] = *(const uint4*)(qkvlo + src);
    }
    __syncthreads();
#pragma unroll
    for (int it = 0; it < 2; it++) {
        const int idx = it * 256 + tid;
        const int d = idx >> 3, ch = idx & 7;
        uint4 oh, ol;
        uint16_t* ph = (uint16_t*)&oh;
        uint16_t* pl = (uint16_t*)&ol;
#pragma unroll
        for (int si = 0; si < 8; si++) {
            ph[si] = th[ch * 8 + si][d];
            pl[si] = tl[ch * 8 + si][d];
        }
        const size_t dst = ((size_t)(bh * 64) + d) * S_LEN + s0 + ch * 8;
        *(uint4*)(vthi + dst) = oh;
        *(uint4*)(vtlo + dst) = ol;
    }
}

// ---------------- HMMA flash attention -----------------------------------
// block: 64 q-rows x one (b,h); 4 warps (16 q each); 64-key tiles, 2-stage cp.async.
#define AT_QHI   0
#define AT_QLO   8192
#define AT_STAGE 16384
#define AT_STSZ  32768        // KHI 8K | KLO 8K | VHI 8K | VLO 8K
#define AT_MASK  (AT_STAGE + 2 * AT_STSZ)
#define AT_SMEM  (AT_MASK + 2 * 256 + 256)

__global__ __launch_bounds__(128)
void attn_mma(const __nv_bfloat16* __restrict__ qkvhi, const __nv_bfloat16* __restrict__ qkvlo,
              const __nv_bfloat16* __restrict__ vthi, const __nv_bfloat16* __restrict__ vtlo,
              const int* __restrict__ mask,
              __nv_bfloat16* __restrict__ ctxhi, __nv_bfloat16* __restrict__ ctxlo)
{
    extern __shared__ __align__(1024) char smem[];
    const uint32_t sb = smem_u32(smem);
    const int tid  = threadIdx.x;
    const int lane = tid & 31;
    const int wid  = tid >> 5;
    const int q0   = blockIdx.x * 64;
    const int bh   = blockIdx.y;
    const int b    = bh >> 4, h = bh & 15;

    // ---- load Q tile (hi/lo) into smem (once) ----
#pragma unroll
    for (int it = 0; it < 4; it++) {
        const int idx = it * 128 + tid;
        const int row = idx >> 3, ch = idx & 7;
        const size_t src = (size_t)(b * S_LEN + q0 + row) * 3072 + h * 64 + ch * 8;
        const uint32_t d = sw128((uint32_t)(row * 128 + ch * 16));
        *(uint4*)(smem + AT_QHI + d) = *(const uint4*)(qkvhi + src);
        *(uint4*)(smem + AT_QLO + d) = *(const uint4*)(qkvlo + src);
    }

    auto issue = [&](int t) {
        const uint32_t stg = sb + AT_STAGE + (t & 1) * AT_STSZ;
        const int kt = t * 64;
        // K rows (keys) from qkv cols [1024..2048), V rows (dims) from vt
#pragma unroll
        for (int it = 0; it < 4; it++) {
            const int idx = it * 128 + tid;
            const int row = idx >> 3, ch = idx & 7;
            const uint32_t d = sw128((uint32_t)(row * 128 + ch * 16));
            const size_t ksrc = (size_t)(b * S_LEN + kt + row) * 3072 + 1024 + h * 64 + ch * 8;
            const size_t vsrc = ((size_t)(bh * 64) + row) * S_LEN + kt + ch * 8;
            CP_ASYNC16(stg +         d, qkvhi + ksrc);
            CP_ASYNC16(stg +  8192 + d, qkvlo + ksrc);
            CP_ASYNC16(stg + 16384 + d, vthi + vsrc);
            CP_ASYNC16(stg + 24576 + d, vtlo + vsrc);
        }
        CP_COMMIT;
        if (tid < 64) {
            float* mp = (float*)(smem + AT_MASK + (t & 1) * 256);
            mp[tid] = mask[b * S_LEN + kt + tid] ? 0.f : -1e9f;
        }
    };

    issue(0);
    issue(1);

    // ---- preload Q fragments ----
    uint32_t qoffb;
    {
        const int m  = wid * 16 + (lane & 7) + 8 * ((lane >> 3) & 1);
        const int ak = (lane >> 4) * 16;
        qoffb = (uint32_t)(m * 128 + ak);
    }
    uint32_t boffA[4];
    {
        const int bk = ((lane >> 3) & 1) * 16;
#pragma unroll
        for (int jg = 0; jg < 4; jg++) {
            const int n = jg * 16 + (lane & 7) + 8 * (lane >> 4);
            boffA[jg] = (uint32_t)(n * 128 + bk);
        }
    }
    __syncthreads();   // Q smem visible
    uint32_t qh[4][4], ql[4][4];
#pragma unroll
    for (int ks = 0; ks < 4; ks++) {
        ldsm_x4(qh[ks][0], qh[ks][1], qh[ks][2], qh[ks][3], sb + AT_QHI + sw128(qoffb + ks * 32));
        ldsm_x4(ql[ks][0], ql[ks][1], ql[ks][2], ql[ks][3], sb + AT_QLO + sw128(qoffb + ks * 32));
    }

    float o[8][4];
#pragma unroll
    for (int j = 0; j < 8; j++)
#pragma unroll
        for (int r = 0; r < 4; r++) o[j][r] = 0.f;
    float m0 = -1e30f, m1 = -1e30f, l0 = 0.f, l1 = 0.f;

    const int ntiles = S_LEN / 64;
    for (int t = 0; t < ntiles; t++) {
        if (t == ntiles - 1) { CP_WAIT0; } else { CP_WAIT1; }
        __syncthreads();
        const uint32_t stg = sb + AT_STAGE + (t & 1) * AT_STSZ;

        // --- scores: 3-term split QK^T ---
        float s[8][4];
#pragma unroll
        for (int j = 0; j < 8; j++)
#pragma unroll
            for (int r = 0; r < 4; r++) s[j][r] = 0.f;
#pragma unroll
        for (int ks = 0; ks < 4; ks++) {
#pragma unroll
            for (int jg = 0; jg < 4; jg++) {
                uint32_t kh[4], kl[4];
                ldsm_x4(kh[0], kh[1], kh[2], kh[3], stg +        sw128(boffA[jg] + ks * 32));
                ldsm_x4(kl[0], kl[1], kl[2], kl[3], stg + 8192 + sw128(boffA[jg] + ks * 32));
                const int j0 = 2 * jg, j1 = 2 * jg + 1;
                mma_bf16(s[j0], qh[ks][0], qh[ks][1], qh[ks][2], qh[ks][3], kh[0], kh[1]);
                mma_bf16(s[j1], qh[ks][0], qh[ks][1], qh[ks][2], qh[ks][3], kh[2], kh[3]);
                mma_bf16(s[j0], qh[ks][0], qh[ks][1], qh[ks][2], qh[ks][3], kl[0], kl[1]);
                mma_bf16(s[j1], qh[ks][0], qh[ks][1], qh[ks][2], qh[ks][3], kl[2], kl[3]);
                mma_bf16(s[j0], ql[ks][0], ql[ks][1], ql[ks][2], ql[ks][3], kh[0], kh[1]);
                mma_bf16(s[j1], ql[ks][0], ql[ks][1], ql[ks][2], ql[ks][3], kh[2], kh[3]);
            }
        }
        // --- scale + mask ---
        const float* madd = (const float*)(smem + AT_MASK + (t & 1) * 256);
#pragma unroll
        for (int j = 0; j < 8; j++) {
            const int c0 = j * 8 + (lane & 3) * 2;
            const float ma = madd[c0], mb = madd[c0 + 1];
            s[j][0] = s[j][0] * 0.125f + ma;
            s[j][1] = s[j][1] * 0.125f + mb;
            s[j][2] = s[j][2] * 0.125f + ma;
            s[j][3] = s[j][3] * 0.125f + mb;
        }
        // --- online softmax (2 rows per thread) ---
        float mx0 = s[0][0], mx1 = s[0][2];
#pragma unroll
        for (int j = 0; j < 8; j++) {
            mx0 = fmaxf(mx0, fmaxf(s[j][0], s[j][1]));
            mx1 = fmaxf(mx1, fmaxf(s[j][2], s[j][3]));
        }
        mx0 = fmaxf(mx0, __shfl_xor_sync(0xffffffff, mx0, 1));
        mx0 = fmaxf(mx0, __shfl_xor_sync(0xffffffff, mx0, 2));
        mx1 = fmaxf(mx1, __shfl_xor_sync(0xffffffff, mx1, 1));
        mx1 = fmaxf(mx1, __shfl_xor_sync(0xffffffff, mx1, 2));
        const float mn0 = fmaxf(m0, mx0), mn1 = fmaxf(m1, mx1);
        const float cr0 = __expf(m0 - mn0), cr1 = __expf(m1 - mn1);
        m0 = mn0; m1 = mn1; l0 *= cr0; l1 *= cr1;
#pragma unroll
        for (int j = 0; j < 8; j++) {
            o[j][0] *= cr0; o[j][1] *= cr0; o[j][2] *= cr1; o[j][3] *= cr1;
            s[j][0] = __expf(s[j][0] - m0);
            s[j][1] = __expf(s[j][1] - m0);
            s[j][2] = __expf(s[j][2] - m1);
            s[j][3] = __expf(s[j][3] - m1);
            l0 += s[j][0] + s[j][1];
            l1 += s[j][2] + s[j][3];
        }
        // --- PV: 3-term split, P fragments built from score fragments ---
#pragma unroll
        for (int kk = 0; kk < 4; kk++) {
            uint32_t ph[4], pl[4];
            split2(s[2 * kk][0],     s[2 * kk][1],     ph[0], pl[0]);
            split2(s[2 * kk][2],     s[2 * kk][3],     ph[1], pl[1]);
            split2(s[2 * kk + 1][0], s[2 * kk + 1][1], ph[2], pl[2]);
            split2(s[2 * kk + 1][2], s[2 * kk + 1][3], ph[3], pl[3]);
#pragma unroll
            for (int jg = 0; jg < 4; jg++) {
                uint32_t vh[4], vl[4];
                ldsm_x4(vh[0], vh[1], vh[2], vh[3], stg + 16384 + sw128(boffA[jg] + kk * 32));
                ldsm_x4(vl[0], vl[1], vl[2], vl[3], stg + 24576 + sw128(boffA[jg] + kk * 32));
                const int j0 = 2 * jg, j1 = 2 * jg + 1;
                mma_bf16(o[j0], ph[0], ph[1], ph[2], ph[3], vh[0], vh[1]);
                mma_bf16(o[j1], ph[0], ph[1], ph[2], ph[3], vh[2], vh[3]);
                mma_bf16(o[j0], pl[0], pl[1], pl[2], pl[3], vh[0], vh[1]);
                mma_bf16(o[j1], pl[0], pl[1], pl[2], pl[3], vh[2], vh[3]);
                mma_bf16(o[j0], ph[0], ph[1], ph[2], ph[3], vl[0], vl[1]);
                mma_bf16(o[j1], ph[0], ph[1], ph[2], ph[3], vl[2], vl[3]);
            }
        }
        __syncthreads();
        if (t + 2 < ntiles) issue(t + 2);
    }

    // ---- finalize ----
    l0 += __shfl_xor_sync(0xffffffff, l0, 1);
    l0 += __shfl_xor_sync(0xffffffff, l0, 2);
    l1 += __shfl_xor_sync(0xffffffff, l1, 1);
    l1 += __shfl_xor_sync(0xffffffff, l1, 2);
    const float inv0 = 1.f / l0, inv1 = 1.f / l1;
    const size_t gr0 = (size_t)(b * S_LEN + q0 + wid * 16 + (lane >> 2));
    const size_t gr1 = gr0 + 8;
#pragma unroll
    for (int j = 0; j < 8; j++) {
        const int col = h * 64 + j * 8 + (lane & 3) * 2;
        uint32_t hh, ll;
        split2(o[j][0] * inv0, o[j][1] * inv0, hh, ll);
        *(uint32_t*)(ctxhi + gr0 * D_DIM + col) = hh;
        *(uint32_t*)(ctxlo + gr0 * D_DIM + col) = ll;
        split2(o[j][2] * inv1, o[j][3] * inv1, hh, ll);
        *(uint32_t*)(ctxhi + gr1 * D_DIM + col) = hh;
        *(uint32_t*)(ctxlo + gr1 * D_DIM + col) = ll;
    }
}

// ---------------- LayerNorm (unbiased std, eps on std), optional split ----
template<bool SPLIT>
__global__ __launch_bounds__(256)
void ln_kernel(const float* __restrict__ x, const float* __restrict__ g,
               const float* __restrict__ be, float* __restrict__ out,
               __nv_bfloat16* __restrict__ ohi, __nv_bfloat16* __restrict__ olo)
{
    __shared__ float red[256];
    const int row = blockIdx.x;
    const int tid = threadIdx.x;

    float4 xv = ((const float4*)(x + (size_t)row * D_DIM))[tid];
    red[tid] = xv.x + xv.y + xv.z + xv.w;
    __syncthreads();
    for (int off = 128; off > 0; off >>= 1) {
        if (tid < off) red[tid] += red[tid + off];
        __syncthreads();
    }
    const float mean = red[0] * (1.f / (float)D_DIM);
    __syncthreads();

    float dx0 = xv.x - mean, dx1 = xv.y - mean, dx2 = xv.z - mean, dx3 = xv.w - mean;
    red[tid] = dx0 * dx0 + dx1 * dx1 + dx2 * dx2 + dx3 * dx3;
    __syncthreads();
    for (int off = 128; off > 0; off >>= 1) {
        if (tid < off) red[tid] += red[tid + off];
        __syncthreads();
    }
    const float var  = red[0] * (1.f / (float)(D_DIM - 1));
    const float istd = 1.f / (sqrtf(var) + 1e-6f);

    float4 gv  = ((const float4*)g)[tid];
    float4 bev = ((const float4*)be)[tid];
    float4 oo;
    oo.x = gv.x * dx0 * istd + bev.x;
    oo.y = gv.y * dx1 * istd + bev.y;
    oo.z = gv.z * dx2 * istd + bev.z;
    oo.w = gv.w * dx3 * istd + bev.w;
    ((float4*)(out + (size_t)row * D_DIM))[tid] = oo;
    if (SPLIT) {
        uint32_t h0, l0, h1, l1;
        split2(oo.x, oo.y, h0, l0);
        split2(oo.z, oo.w, h1, l1);
        ((uint2*)(ohi + (size_t)row * D_DIM))[tid] = make_uint2(h0, h1);
        ((uint2*)(olo + (size_t)row * D_DIM))[tid] = make_uint2(l0, l1);
    }
}

// ---------------- host launcher -----------------------------------------
extern "C" void kernel_launch(void* const* d_in, const int* in_sizes, int n_in,
                              void* d_out, int out_size)
{
    const float* x    = (const float*)d_in[0];
    const int*   mask = (const int*)  d_in[1];
    const float* Wq   = (const float*)d_in[2];
    const float* bq   = (const float*)d_in[3];
    const float* Wk   = (const float*)d_in[4];
    const float* bk   = (const float*)d_in[5];
    const float* Wv   = (const float*)d_in[6];
    const float* bv   = (const float*)d_in[7];
    const float* Wo   = (const float*)d_in[8];
    const float* bo   = (const float*)d_in[9];
    const float* W1   = (const float*)d_in[10];
    const float* b1   = (const float*)d_in[11];
    const float* W2   = (const float*)d_in[12];
    const float* b2   = (const float*)d_in[13];
    const float* g1   = (const float*)d_in[14];
    const float* be1  = (const float*)d_in[15];
    const float* g2   = (const float*)d_in[16];
    const float* be2  = (const float*)d_in[17];
    float* out = (float*)d_out;

    __nv_bfloat16 *xhi, *xlo, *wqkvhi, *wqkvlo, *wohi, *wolo, *w1hi, *w1lo, *w2hi, *w2lo;
    __nv_bfloat16 *qkvhi, *qkvlo, *vthi, *vtlo, *ctxhi, *ctxlo, *x1hi, *x1lo, *hhi, *hlo;
    float *bqkv, *y1, *x1f, *y2;
    cudaGetSymbolAddress((void**)&xhi, g_xhi);       cudaGetSymbolAddress((void**)&xlo, g_xlo);
    cudaGetSymbolAddress((void**)&wqkvhi, g_wqkvhi); cudaGetSymbolAddress((void**)&wqkvlo, g_wqkvlo);
    cudaGetSymbolAddress((void**)&wohi, g_wohi);     cudaGetSymbolAddress((void**)&wolo, g_wolo);
    cudaGetSymbolAddress((void**)&w1hi, g_w1hi);     cudaGetSymbolAddress((void**)&w1lo, g_w1lo);
    cudaGetSymbolAddress((void**)&w2hi, g_w2hi);     cudaGetSymbolAddress((void**)&w2lo, g_w2lo);
    cudaGetSymbolAddress((void**)&bqkv, g_bqkv);
    cudaGetSymbolAddress((void**)&qkvhi, g_qkvhi);   cudaGetSymbolAddress((void**)&qkvlo, g_qkvlo);
    cudaGetSymbolAddress((void**)&vthi, g_vthi);     cudaGetSymbolAddress((void**)&vtlo, g_vtlo);
    cudaGetSymbolAddress((void**)&ctxhi, g_ctxhi);   cudaGetSymbolAddress((void**)&ctxlo, g_ctxlo);
    cudaGetSymbolAddress((void**)&x1hi, g_x1hi);     cudaGetSymbolAddress((void**)&x1lo, g_x1lo);
    cudaGetSymbolAddress((void**)&hhi, g_hhi);       cudaGetSymbolAddress((void**)&hlo, g_hlo);
    cudaGetSymbolAddress((void**)&y1, g_y1);
    cudaGetSymbolAddress((void**)&x1f, g_x1f);
    cudaGetSymbolAddress((void**)&y2, g_y2);

    cudaFuncSetAttribute(hmma_gemm2<0, false, true >, cudaFuncAttributeMaxDynamicSharedMemorySize, GEMM_SMEM);
    cudaFuncSetAttribute(hmma_gemm2<1, false, false>, cudaFuncAttributeMaxDynamicSharedMemorySize, GEMM_SMEM);
    cudaFuncSetAttribute(hmma_gemm2<1, true,  false>, cudaFuncAttributeMaxDynamicSharedMemorySize, GEMM_SMEM);
    cudaFuncSetAttribute(attn_mma, cudaFuncAttributeMaxDynamicSharedMemorySize, AT_SMEM);

    // ---- conversions (weights + x) ----
    const int CB = 256;
    convsplit<<<(M_ROWS * D_DIM / 4 + CB - 1) / CB, CB>>>(x,  xhi, xlo, M_ROWS * D_DIM / 4);
    convsplit<<<(D_DIM * D_DIM / 4 + CB - 1) / CB, CB>>>(Wq, wqkvhi,                 wqkvlo,                 D_DIM * D_DIM / 4);
    convsplit<<<(D_DIM * D_DIM / 4 + CB - 1) / CB, CB>>>(Wk, wqkvhi + D_DIM * D_DIM, wqkvlo + D_DIM * D_DIM, D_DIM * D_DIM / 4);
    convsplit<<<(D_DIM * D_DIM / 4 + CB - 1) / CB, CB>>>(Wv, wqkvhi + 2 * D_DIM * D_DIM, wqkvlo + 2 * D_DIM * D_DIM, D_DIM * D_DIM / 4);
    convsplit<<<(D_DIM * D_DIM / 4 + CB - 1) / CB, CB>>>(Wo, wohi, wolo, D_DIM * D_DIM / 4);
    convsplit<<<(DFF_D * D_DIM / 4 + CB - 1) / CB, CB>>>(W1, w1hi, w1lo, DFF_D * D_DIM / 4);
    convsplit<<<(D_DIM * DFF_D / 4 + CB - 1) / CB, CB>>>(W2, w2hi, w2lo, D_DIM * DFF_D / 4);
    concat3<<<12, 256>>>(bq, bk, bv, bqkv);

    // ---- fused QKV projection (split output) ----
    hmma_gemm2<1, false, false><<<dim3(3 * D_DIM / 128, M_ROWS / 128), 256, GEMM_SMEM>>>(
        xhi, xlo, wqkvhi, wqkvlo, bqkv, nullptr, nullptr, qkvhi, qkvlo, M_ROWS, 3 * D_DIM, D_DIM);

    // ---- V transpose ----
    vtrans_kernel<<<dim3(S_LEN / 64, B_SZ * NHEAD), 256>>>(qkvhi, qkvlo, vthi, vtlo);

    // ---- attention ----
    attn_mma<<<dim3(S_LEN / 64, B_SZ * NHEAD), 128, AT_SMEM>>>(
        qkvhi, qkvlo, vthi, vtlo, mask, ctxhi, ctxlo);

    // ---- O projection + residual, LN1 (emits split) ----
    hmma_gemm2<0, false, true><<<dim3(D_DIM / 128, M_ROWS / 128), 256, GEMM_SMEM>>>(
        ctxhi, ctxlo, wohi, wolo, bo, x, y1, nullptr, nullptr, M_ROWS, D_DIM, D_DIM);
    ln_kernel<true><<<M_ROWS, 256>>>(y1, g1, be1, x1f, x1hi, x1lo);

    // ---- FFN ----
    hmma_gemm2<1, true, false><<<dim3(DFF_D / 128, M_ROWS / 128), 256, GEMM_SMEM>>>(
        x1hi, x1lo, w1hi, w1lo, b1, nullptr, nullptr, hhi, hlo, M_ROWS, DFF_D, D_DIM);
    hmma_gemm2<0, false, true><<<dim3(D_DIM / 128, M_ROWS / 128), 256, GEMM_SMEM>>>(
        hhi, hlo, w2hi, w2lo, b2, x1f, y2, nullptr, nullptr, M_ROWS, D_DIM, DFF_D);
    ln_kernel<false><<<M_ROWS, 256>>>(y2, g2, be2, out, nullptr, nullptr);
}